// round 9
// baseline (speedup 1.0000x reference)
#include <cuda_runtime.h>
#include <cstdint>

#define B_   4
#define N_   2048
#define DIM_ 1024
#define H_   16
#define HD_  64
#define E3_  3072
#define M_   8192
#define SCALE_ 0.125f

__device__ float g_q[(size_t)B_ * H_ * N_ * HD_];
__device__ float g_k[(size_t)B_ * H_ * N_ * HD_];
__device__ float g_v[(size_t)B_ * H_ * N_ * HD_];

// ---------------------------------------------------------------------------
// helpers
// ---------------------------------------------------------------------------
__device__ __forceinline__ float tf32r(float x) {
    uint32_t u;
    asm("cvt.rna.tf32.f32 %0, %1;" : "=r"(u) : "f"(x));
    return __uint_as_float(u);
}
__device__ __forceinline__ uint32_t tf32u(float x) {
    uint32_t u;
    asm("cvt.rna.tf32.f32 %0, %1;" : "=r"(u) : "f"(x));
    return u;
}
__device__ __forceinline__ uint32_t smem_u32(const void* p) {
    uint32_t a;
    asm("{ .reg .u64 t; cvta.to.shared.u64 t, %1; cvt.u32.u64 %0, t; }"
        : "=r"(a) : "l"(p));
    return a;
}
__device__ __forceinline__ void cpasync16(uint32_t dst, const void* src) {
    asm volatile("cp.async.cg.shared.global [%0], [%1], 16;"
                 :: "r"(dst), "l"(src) : "memory");
}
__device__ __forceinline__ void mma8(float* d,
                                     uint32_t a0, uint32_t a1, uint32_t a2, uint32_t a3,
                                     uint32_t b0, uint32_t b1) {
    asm volatile(
        "mma.sync.aligned.m16n8k8.row.col.f32.tf32.tf32.f32 "
        "{%0,%1,%2,%3}, {%4,%5,%6,%7}, {%8,%9}, {%0,%1,%2,%3};"
        : "+f"(d[0]), "+f"(d[1]), "+f"(d[2]), "+f"(d[3])
        : "r"(a0), "r"(a1), "r"(a2), "r"(a3), "r"(b0), "r"(b1));
}
__device__ __forceinline__ uint32_t f2u(float x) { return __float_as_uint(x); }

// ---------------------------------------------------------------------------
// Kernel 1: QKV projection (unchanged from R8 pass).
// CTA 256x128, BK=32 double-buffered, 512 thr, 16 warps, warp tile 64x32.
// ---------------------------------------------------------------------------
#define GSTR 36
#define A_TILE (256 * GSTR)
#define B_TILE (128 * GSTR)
#define OFF_A1 A_TILE
#define OFF_B0 (2 * A_TILE)
#define OFF_B1 (2 * A_TILE + B_TILE)
#define G_SMEM_BYTES ((2 * A_TILE + 2 * B_TILE) * 4)   // 110592 B

__global__ __launch_bounds__(512) void qkv_mma_kernel(
    const float* __restrict__ X, const float* __restrict__ W,
    const float* __restrict__ bias)
{
    extern __shared__ float smg[];
    const uint32_t sbase = smem_u32(smg);

    const int tid  = threadIdx.x;
    const int wid  = tid >> 5;
    const int lane = tid & 31;
    const int g    = lane >> 2;
    const int t    = lane & 3;
    const int warpM = (wid >> 2) * 64;
    const int warpN = (wid & 3) * 32;
    const int mBase = blockIdx.y * 256;
    const int eBase = blockIdx.x * 128;

    const int arow  = tid >> 1;
    const int ahalf = tid & 1;
    const int brow  = tid >> 2;
    const int bq    = tid & 3;

    auto load_stage = [&](int buf, int s) {
        const int k0 = s * 32;
        const float* ax = X + (size_t)(mBase + arow) * DIM_ + k0 + ahalf * 16;
        const float* bx = W + (size_t)(eBase + brow) * DIM_ + k0 + bq * 8;
        uint32_t da = sbase + (uint32_t)(((buf ? OFF_A1 : 0) + arow * GSTR + ahalf * 16) * 4);
        uint32_t db = sbase + (uint32_t)(((buf ? OFF_B1 : OFF_B0) + brow * GSTR + bq * 8) * 4);
        #pragma unroll
        for (int c = 0; c < 4; c++) cpasync16(da + c * 16, ax + c * 4);
        #pragma unroll
        for (int c = 0; c < 2; c++) cpasync16(db + c * 16, bx + c * 4);
        asm volatile("cp.async.commit_group;" ::: "memory");
    };

    float acc[4][4][4];
    #pragma unroll
    for (int i = 0; i < 4; i++)
        #pragma unroll
        for (int j = 0; j < 4; j++)
            #pragma unroll
            for (int r = 0; r < 4; r++) acc[i][j][r] = 0.0f;

    load_stage(0, 0);
    load_stage(1, 1);

    for (int s = 0; s < DIM_ / 32; s++) {
        const int buf = s & 1;
        if (s < DIM_ / 32 - 1) asm volatile("cp.async.wait_group 1;" ::: "memory");
        else                   asm volatile("cp.async.wait_group 0;" ::: "memory");
        __syncthreads();

        const float* A   = smg + (buf ? OFF_A1 : 0);
        const float* Bsm = smg + (buf ? OFF_B1 : OFF_B0);
        #pragma unroll
        for (int ks = 0; ks < 4; ks++) {
            const int kk = ks * 8 + t;
            uint32_t af[4][4];
            #pragma unroll
            for (int mt = 0; mt < 4; mt++) {
                const int r = warpM + mt * 16 + g;
                af[mt][0] = tf32u(A[r * GSTR + kk]);
                af[mt][1] = tf32u(A[(r + 8) * GSTR + kk]);
                af[mt][2] = tf32u(A[r * GSTR + kk + 4]);
                af[mt][3] = tf32u(A[(r + 8) * GSTR + kk + 4]);
            }
            #pragma unroll
            for (int nt = 0; nt < 4; nt++) {
                const int n = warpN + nt * 8 + g;
                uint32_t b0 = tf32u(Bsm[n * GSTR + kk]);
                uint32_t b1 = tf32u(Bsm[n * GSTR + kk + 4]);
                #pragma unroll
                for (int mt = 0; mt < 4; mt++)
                    mma8(acc[mt][nt], af[mt][0], af[mt][1], af[mt][2], af[mt][3], b0, b1);
            }
        }
        __syncthreads();
        if (s + 2 < DIM_ / 32) load_stage(buf, s + 2);
    }

    #pragma unroll
    for (int nt = 0; nt < 4; nt++) {
        const int c0   = eBase + warpN + nt * 8 + 2 * t;
        const int tsel = c0 >> 10;
        const int rem  = c0 & (DIM_ - 1);
        const int h    = rem >> 6;
        const int hd   = rem & (HD_ - 1);
        float* dst = (tsel == 0) ? g_q : ((tsel == 1) ? g_k : g_v);
        const float sc = (tsel == 0) ? SCALE_ : 1.0f;
        const float bb0 = __ldg(bias + c0);
        const float bb1 = __ldg(bias + c0 + 1);
        #pragma unroll
        for (int mt = 0; mt < 4; mt++) {
            const int r0 = mBase + warpM + mt * 16 + g;
            #pragma unroll
            for (int half = 0; half < 2; half++) {
                const int row = r0 + half * 8;
                const int bi  = row >> 11;
                const int n   = row & (N_ - 1);
                float2 v;
                v.x = tf32r((acc[mt][nt][half * 2 + 0] + bb0) * sc);
                v.y = tf32r((acc[mt][nt][half * 2 + 1] + bb1) * sc);
                *(float2*)(dst + ((((size_t)bi * H_ + h) * N_ + n) * HD_ + hd)) = v;
            }
        }
    }
}

// ---------------------------------------------------------------------------
// Kernel 2: flash attention, mma.sync tf32, shfl-transposed P,
// DOUBLE-BUFFERED K/V (cp.async one tile ahead).
// grid (N/128, B*H), 128 thr, 4 warps x 32 q-rows, key tile 64.
// smem: Qs[128][68] + 2*(Ks[64][68] + Vs[64][72]) = 106496 B -> 2 CTAs/SM.
// ---------------------------------------------------------------------------
#define QSTR 68
#define KSTR 68
#define VSTR 72
#define KVTILE (64 * KSTR + 64 * VSTR)         // floats per kv buffer
#define AOFF_KV (128 * QSTR)
#define ATT_SMEM ((AOFF_KV + 2 * KVTILE) * 4)  // 106496 B

__global__ __launch_bounds__(128, 2) void attn_kernel6(float* __restrict__ out)
{
    extern __shared__ float sm[];
    float* Qs = sm;
    const uint32_t sbase = smem_u32(sm);

    const int tid  = threadIdx.x;
    const int wid  = tid >> 5;
    const int lane = tid & 31;
    const int g    = lane >> 2;
    const int t    = lane & 3;
    const int warpQ = wid * 32;
    const int odd  = lane & 1;
    const int src0 = (lane & ~3) | ((lane & 3) >> 1);
    const int src1 = src0 + 2;

    const int bh = blockIdx.y;
    const int bi = bh >> 4;
    const int h  = bh & 15;
    const int q0 = blockIdx.x * 128;

    const float* Qg = g_q + (size_t)bh * N_ * HD_ + (size_t)q0 * HD_;
    const float* Kg = g_k + (size_t)bh * N_ * HD_;
    const float* Vg = g_v + (size_t)bh * N_ * HD_;

    // per-thread slice for K/V loads: row = tid>>1 .. covers 64 rows x 2 halves
    const int kvrow  = tid >> 1;          // 0..63
    const int kvhalf = (tid & 1) * 32;    // 0 or 32 (floats)

    auto load_kv = [&](int kt, int buf) {
        const float* kp = Kg + (size_t)(kt * 64 + kvrow) * HD_ + kvhalf;
        const float* vp = Vg + (size_t)(kt * 64 + kvrow) * HD_ + kvhalf;
        uint32_t dk = sbase + (uint32_t)((AOFF_KV + buf * KVTILE + kvrow * KSTR + kvhalf) * 4);
        uint32_t dv = sbase + (uint32_t)((AOFF_KV + buf * KVTILE + 64 * KSTR + kvrow * VSTR + kvhalf) * 4);
        #pragma unroll
        for (int c = 0; c < 8; c++) cpasync16(dk + c * 16, kp + c * 4);
        #pragma unroll
        for (int c = 0; c < 8; c++) cpasync16(dv + c * 16, vp + c * 4);
        asm volatile("cp.async.commit_group;" ::: "memory");
    };

    // load Q 128x64 (plain loads, overlapped with first K/V cp.async)
    load_kv(0, 0);
    #pragma unroll
    for (int s = 0; s < 16; s++) {
        int slot = tid + s * 128;
        int row = slot >> 4;
        int c4  = (slot & 15) << 2;
        *(float4*)(Qs + row * QSTR + c4) = *(const float4*)(Qg + row * HD_ + c4);
    }

    float o[2][8][4];
    float mrow[2][2], lrow[2][2];
    #pragma unroll
    for (int mt = 0; mt < 2; mt++) {
        mrow[mt][0] = -1e30f; mrow[mt][1] = -1e30f;
        lrow[mt][0] = 0.0f;   lrow[mt][1] = 0.0f;
        #pragma unroll
        for (int nt = 0; nt < 8; nt++)
            #pragma unroll
            for (int r = 0; r < 4; r++) o[mt][nt][r] = 0.0f;
    }

    const int NT = N_ / 64;
    for (int kt = 0; kt < NT; kt++) {
        const int buf = kt & 1;
        __syncthreads();   // all warps done computing kt-1 (read buf^1) -> safe to refill
        if (kt + 1 < NT) {
            load_kv(kt + 1, buf ^ 1);
            asm volatile("cp.async.wait_group 1;" ::: "memory");  // kt's group done
        } else {
            asm volatile("cp.async.wait_group 0;" ::: "memory");
        }
        __syncthreads();   // kt's K/V visible to all warps

        const float* Ks = sm + AOFF_KV + buf * KVTILE;
        const float* Vs = Ks + 64 * KSTR;

        // stage 1: S = Q K^T  (warp: 32q x 64k)
        float s_[2][8][4];
        #pragma unroll
        for (int mt = 0; mt < 2; mt++)
            #pragma unroll
            for (int nt = 0; nt < 8; nt++)
                #pragma unroll
                for (int r = 0; r < 4; r++) s_[mt][nt][r] = 0.0f;

        #pragma unroll
        for (int ks = 0; ks < 8; ks++) {
            const int kk = ks * 8 + t;
            uint32_t af[2][4];
            #pragma unroll
            for (int mt = 0; mt < 2; mt++) {
                const int r = warpQ + mt * 16 + g;
                af[mt][0] = f2u(Qs[r * QSTR + kk]);
                af[mt][1] = f2u(Qs[(r + 8) * QSTR + kk]);
                af[mt][2] = f2u(Qs[r * QSTR + kk + 4]);
                af[mt][3] = f2u(Qs[(r + 8) * QSTR + kk + 4]);
            }
            #pragma unroll
            for (int nt = 0; nt < 8; nt++) {
                const int n = nt * 8 + g;
                uint32_t b0 = f2u(Ks[n * KSTR + kk]);
                uint32_t b1 = f2u(Ks[n * KSTR + kk + 4]);
                #pragma unroll
                for (int mt = 0; mt < 2; mt++)
                    mma8(s_[mt][nt], af[mt][0], af[mt][1], af[mt][2], af[mt][3], b0, b1);
            }
        }

        // online softmax; rounded P kept in registers
        #pragma unroll
        for (int mt = 0; mt < 2; mt++) {
            float mx0 = -1e30f, mx1 = -1e30f;
            #pragma unroll
            for (int nt = 0; nt < 8; nt++) {
                mx0 = fmaxf(mx0, fmaxf(s_[mt][nt][0], s_[mt][nt][1]));
                mx1 = fmaxf(mx1, fmaxf(s_[mt][nt][2], s_[mt][nt][3]));
            }
            mx0 = fmaxf(mx0, __shfl_xor_sync(0xffffffffu, mx0, 1));
            mx0 = fmaxf(mx0, __shfl_xor_sync(0xffffffffu, mx0, 2));
            mx1 = fmaxf(mx1, __shfl_xor_sync(0xffffffffu, mx1, 1));
            mx1 = fmaxf(mx1, __shfl_xor_sync(0xffffffffu, mx1, 2));
            const float nm0 = fmaxf(mrow[mt][0], mx0);
            const float nm1 = fmaxf(mrow[mt][1], mx1);
            const float corr0 = __expf(mrow[mt][0] - nm0);
            const float corr1 = __expf(mrow[mt][1] - nm1);
            mrow[mt][0] = nm0; mrow[mt][1] = nm1;

            float rs0 = 0.0f, rs1 = 0.0f;
            #pragma unroll
            for (int nt = 0; nt < 8; nt++) {
                float p0 = tf32r(__expf(s_[mt][nt][0] - nm0));
                float p1 = tf32r(__expf(s_[mt][nt][1] - nm0));
                float p2 = tf32r(__expf(s_[mt][nt][2] - nm1));
                float p3 = tf32r(__expf(s_[mt][nt][3] - nm1));
                rs0 += p0 + p1;  rs1 += p2 + p3;
                s_[mt][nt][0] = p0; s_[mt][nt][1] = p1;
                s_[mt][nt][2] = p2; s_[mt][nt][3] = p3;
            }
            rs0 += __shfl_xor_sync(0xffffffffu, rs0, 1);
            rs0 += __shfl_xor_sync(0xffffffffu, rs0, 2);
            rs1 += __shfl_xor_sync(0xffffffffu, rs1, 1);
            rs1 += __shfl_xor_sync(0xffffffffu, rs1, 2);
            lrow[mt][0] = lrow[mt][0] * corr0 + rs0;
            lrow[mt][1] = lrow[mt][1] * corr1 + rs1;

            #pragma unroll
            for (int nt = 0; nt < 8; nt++) {
                o[mt][nt][0] *= corr0; o[mt][nt][1] *= corr0;
                o[mt][nt][2] *= corr1; o[mt][nt][3] *= corr1;
            }
        }

        // stage 2: O += P V ; P a-frags via register shfl transpose
        #pragma unroll
        for (int ks = 0; ks < 8; ks++) {
            uint32_t af[2][4];
            #pragma unroll
            for (int mt = 0; mt < 2; mt++) {
                float x0 = __shfl_sync(0xffffffffu, s_[mt][ks][0], src0);
                float x1 = __shfl_sync(0xffffffffu, s_[mt][ks][1], src0);
                float x2 = __shfl_sync(0xffffffffu, s_[mt][ks][2], src0);
                float x3 = __shfl_sync(0xffffffffu, s_[mt][ks][3], src0);
                float y0 = __shfl_sync(0xffffffffu, s_[mt][ks][0], src1);
                float y1 = __shfl_sync(0xffffffffu, s_[mt][ks][1], src1);
                float y2 = __shfl_sync(0xffffffffu, s_[mt][ks][2], src1);
                float y3 = __shfl_sync(0xffffffffu, s_[mt][ks][3], src1);
                af[mt][0] = f2u(odd ? x1 : x0);
                af[mt][1] = f2u(odd ? x3 : x2);
                af[mt][2] = f2u(odd ? y1 : y0);
                af[mt][3] = f2u(odd ? y3 : y2);
            }
            #pragma unroll
            for (int nt = 0; nt < 8; nt++) {
                const int n = nt * 8 + g;
                uint32_t b0 = f2u(Vs[(ks * 8 + t) * VSTR + n]);
                uint32_t b1 = f2u(Vs[(ks * 8 + t + 4) * VSTR + n]);
                #pragma unroll
                for (int mt = 0; mt < 2; mt++)
                    mma8(o[mt][nt], af[mt][0], af[mt][1], af[mt][2], af[mt][3], b0, b1);
            }
        }
    }

    // normalize + store
    #pragma unroll
    for (int mt = 0; mt < 2; mt++) {
        const float inv0 = 1.0f / lrow[mt][0];
        const float inv1 = 1.0f / lrow[mt][1];
        const int n0 = q0 + warpQ + mt * 16 + g;
        float* po0 = out + ((size_t)bi * N_ + n0) * DIM_ + h * HD_;
        float* po1 = out + ((size_t)bi * N_ + n0 + 8) * DIM_ + h * HD_;
        #pragma unroll
        for (int nt = 0; nt < 8; nt++) {
            const int c = nt * 8 + 2 * t;
            *(float2*)(po0 + c) = make_float2(o[mt][nt][0] * inv0, o[mt][nt][1] * inv0);
            *(float2*)(po1 + c) = make_float2(o[mt][nt][2] * inv1, o[mt][nt][3] * inv1);
        }
    }
}

// ---------------------------------------------------------------------------
extern "C" void kernel_launch(void* const* d_in, const int* in_sizes, int n_in,
                              void* d_out, int out_size)
{
    const float* x    = (const float*)d_in[0];
    const float* wqkv = (const float*)d_in[1];
    const float* bqkv = (const float*)d_in[2];
    float* out = (float*)d_out;

    cudaFuncSetAttribute(qkv_mma_kernel,
                         cudaFuncAttributeMaxDynamicSharedMemorySize, G_SMEM_BYTES);
    cudaFuncSetAttribute(attn_kernel6,
                         cudaFuncAttributeMaxDynamicSharedMemorySize, ATT_SMEM);

    dim3 ggrid(E3_ / 128, M_ / 256);   // (24, 32)
    qkv_mma_kernel<<<ggrid, 512, G_SMEM_BYTES>>>(x, wqkv, bqkv);

    dim3 agrid(N_ / 128, B_ * H_);     // (16, 64)
    attn_kernel6<<<agrid, 128, ATT_SMEM>>>(out);
}

// round 10
// speedup vs baseline: 1.4373x; 1.4373x over previous
#include <cuda_runtime.h>
#include <cuda_fp16.h>
#include <cstdint>

#define B_   4
#define N_   2048
#define DIM_ 1024
#define H_   16
#define HD_  64
#define E3_  3072
#define M_   8192
#define SCALE_ 0.125f

// Scratch q/k/v in [B,H,N,HD], fp16 (rounded at GEMM epilogue)
__device__ __half g_q[(size_t)B_ * H_ * N_ * HD_];
__device__ __half g_k[(size_t)B_ * H_ * N_ * HD_];
__device__ __half g_v[(size_t)B_ * H_ * N_ * HD_];

// ---------------------------------------------------------------------------
// helpers
// ---------------------------------------------------------------------------
__device__ __forceinline__ uint32_t tf32u(float x) {
    uint32_t u;
    asm("cvt.rna.tf32.f32 %0, %1;" : "=r"(u) : "f"(x));
    return u;
}
__device__ __forceinline__ uint32_t smem_u32(const void* p) {
    uint32_t a;
    asm("{ .reg .u64 t; cvta.to.shared.u64 t, %1; cvt.u32.u64 %0, t; }"
        : "=r"(a) : "l"(p));
    return a;
}
__device__ __forceinline__ void cpasync16(uint32_t dst, const void* src) {
    asm volatile("cp.async.cg.shared.global [%0], [%1], 16;"
                 :: "r"(dst), "l"(src) : "memory");
}
// tf32: d += a(16x8) * b(8x8)
__device__ __forceinline__ void mma8(float* d,
                                     uint32_t a0, uint32_t a1, uint32_t a2, uint32_t a3,
                                     uint32_t b0, uint32_t b1) {
    asm volatile(
        "mma.sync.aligned.m16n8k8.row.col.f32.tf32.tf32.f32 "
        "{%0,%1,%2,%3}, {%4,%5,%6,%7}, {%8,%9}, {%0,%1,%2,%3};"
        : "+f"(d[0]), "+f"(d[1]), "+f"(d[2]), "+f"(d[3])
        : "r"(a0), "r"(a1), "r"(a2), "r"(a3), "r"(b0), "r"(b1));
}
// fp16: d += a(16x16) * b(16x8), f32 accum
__device__ __forceinline__ void mma16(float* d,
                                      uint32_t a0, uint32_t a1, uint32_t a2, uint32_t a3,
                                      uint32_t b0, uint32_t b1) {
    asm volatile(
        "mma.sync.aligned.m16n8k16.row.col.f32.f16.f16.f32 "
        "{%0,%1,%2,%3}, {%4,%5,%6,%7}, {%8,%9}, {%0,%1,%2,%3};"
        : "+f"(d[0]), "+f"(d[1]), "+f"(d[2]), "+f"(d[3])
        : "r"(a0), "r"(a1), "r"(a2), "r"(a3), "r"(b0), "r"(b1));
}
__device__ __forceinline__ void ldsm_x4(uint32_t* r, uint32_t addr) {
    asm volatile("ldmatrix.sync.aligned.m8n8.x4.shared.b16 {%0,%1,%2,%3}, [%4];"
                 : "=r"(r[0]), "=r"(r[1]), "=r"(r[2]), "=r"(r[3]) : "r"(addr));
}
__device__ __forceinline__ void ldsm_x4t(uint32_t* r, uint32_t addr) {
    asm volatile("ldmatrix.sync.aligned.m8n8.x4.trans.shared.b16 {%0,%1,%2,%3}, [%4];"
                 : "=r"(r[0]), "=r"(r[1]), "=r"(r[2]), "=r"(r[3]) : "r"(addr));
}
__device__ __forceinline__ uint32_t packh2(float lo, float hi) {
    __half2 h = __floats2half2_rn(lo, hi);
    return *(uint32_t*)&h;
}

// ---------------------------------------------------------------------------
// Kernel 1: QKV projection, tf32 mma (unchanged math), fp16 scatter epilogue.
// CTA 256x128, BK=32 double-buffered, 512 thr, 16 warps, warp tile 64x32.
// ---------------------------------------------------------------------------
#define GSTR 36
#define A_TILE (256 * GSTR)
#define B_TILE (128 * GSTR)
#define OFF_A1 A_TILE
#define OFF_B0 (2 * A_TILE)
#define OFF_B1 (2 * A_TILE + B_TILE)
#define G_SMEM_BYTES ((2 * A_TILE + 2 * B_TILE) * 4)

__global__ __launch_bounds__(512) void qkv_mma_kernel(
    const float* __restrict__ X, const float* __restrict__ W,
    const float* __restrict__ bias)
{
    extern __shared__ float smg[];
    const uint32_t sbase = smem_u32(smg);

    const int tid  = threadIdx.x;
    const int wid  = tid >> 5;
    const int lane = tid & 31;
    const int g    = lane >> 2;
    const int t    = lane & 3;
    const int warpM = (wid >> 2) * 64;
    const int warpN = (wid & 3) * 32;
    const int mBase = blockIdx.y * 256;
    const int eBase = blockIdx.x * 128;

    const int arow  = tid >> 1;
    const int ahalf = tid & 1;
    const int brow  = tid >> 2;
    const int bq    = tid & 3;

    auto load_stage = [&](int buf, int s) {
        const int k0 = s * 32;
        const float* ax = X + (size_t)(mBase + arow) * DIM_ + k0 + ahalf * 16;
        const float* bx = W + (size_t)(eBase + brow) * DIM_ + k0 + bq * 8;
        uint32_t da = sbase + (uint32_t)(((buf ? OFF_A1 : 0) + arow * GSTR + ahalf * 16) * 4);
        uint32_t db = sbase + (uint32_t)(((buf ? OFF_B1 : OFF_B0) + brow * GSTR + bq * 8) * 4);
        #pragma unroll
        for (int c = 0; c < 4; c++) cpasync16(da + c * 16, ax + c * 4);
        #pragma unroll
        for (int c = 0; c < 2; c++) cpasync16(db + c * 16, bx + c * 4);
        asm volatile("cp.async.commit_group;" ::: "memory");
    };

    float acc[4][4][4];
    #pragma unroll
    for (int i = 0; i < 4; i++)
        #pragma unroll
        for (int j = 0; j < 4; j++)
            #pragma unroll
            for (int r = 0; r < 4; r++) acc[i][j][r] = 0.0f;

    load_stage(0, 0);
    load_stage(1, 1);

    for (int s = 0; s < DIM_ / 32; s++) {
        const int buf = s & 1;
        if (s < DIM_ / 32 - 1) asm volatile("cp.async.wait_group 1;" ::: "memory");
        else                   asm volatile("cp.async.wait_group 0;" ::: "memory");
        __syncthreads();

        const float* A   = smg + (buf ? OFF_A1 : 0);
        const float* Bsm = smg + (buf ? OFF_B1 : OFF_B0);
        #pragma unroll
        for (int ks = 0; ks < 4; ks++) {
            const int kk = ks * 8 + t;
            uint32_t af[4][4];
            #pragma unroll
            for (int mt = 0; mt < 4; mt++) {
                const int r = warpM + mt * 16 + g;
                af[mt][0] = tf32u(A[r * GSTR + kk]);
                af[mt][1] = tf32u(A[(r + 8) * GSTR + kk]);
                af[mt][2] = tf32u(A[r * GSTR + kk + 4]);
                af[mt][3] = tf32u(A[(r + 8) * GSTR + kk + 4]);
            }
            #pragma unroll
            for (int nt = 0; nt < 4; nt++) {
                const int n = warpN + nt * 8 + g;
                uint32_t b0 = tf32u(Bsm[n * GSTR + kk]);
                uint32_t b1 = tf32u(Bsm[n * GSTR + kk + 4]);
                #pragma unroll
                for (int mt = 0; mt < 4; mt++)
                    mma8(acc[mt][nt], af[mt][0], af[mt][1], af[mt][2], af[mt][3], b0, b1);
            }
        }
        __syncthreads();
        if (s + 2 < DIM_ / 32) load_stage(buf, s + 2);
    }

    // epilogue: bias + scale + fp16 round + scatter (half2 stores)
    #pragma unroll
    for (int nt = 0; nt < 4; nt++) {
        const int c0   = eBase + warpN + nt * 8 + 2 * t;
        const int tsel = c0 >> 10;
        const int rem  = c0 & (DIM_ - 1);
        const int h    = rem >> 6;
        const int hd   = rem & (HD_ - 1);
        __half* dst = (tsel == 0) ? g_q : ((tsel == 1) ? g_k : g_v);
        const float sc = (tsel == 0) ? SCALE_ : 1.0f;
        const float bb0 = __ldg(bias + c0);
        const float bb1 = __ldg(bias + c0 + 1);
        #pragma unroll
        for (int mt = 0; mt < 4; mt++) {
            const int r0 = mBase + warpM + mt * 16 + g;
            #pragma unroll
            for (int half = 0; half < 2; half++) {
                const int row = r0 + half * 8;
                const int bi  = row >> 11;
                const int n   = row & (N_ - 1);
                __half2 hv = __floats2half2_rn(
                    (acc[mt][nt][half * 2 + 0] + bb0) * sc,
                    (acc[mt][nt][half * 2 + 1] + bb1) * sc);
                *(__half2*)(dst + ((((size_t)bi * H_ + h) * N_ + n) * HD_ + hd)) = hv;
            }
        }
    }
}

// ---------------------------------------------------------------------------
// Kernel 2: flash attention, fp16 mma m16n8k16, ldmatrix operands,
// P re-used as A-fragment directly from S c-fragments (no shfl, no smem P).
// grid (N/128, B*H), 128 thr, 4 warps x 32 q-rows, key tile 64.
// smem (halves, stride 72): Qs[128] + Ks[64] + Vs[64] = 36864 B -> 3 CTAs/SM.
// ---------------------------------------------------------------------------
#define QSTRH 72
#define KSTRH 72
#define VSTRH 72
#define HOFF_K (128 * QSTRH)
#define HOFF_V (HOFF_K + 64 * KSTRH)
#define ATT_SMEM ((HOFF_V + 64 * VSTRH) * 2)   // 36864 B

__global__ __launch_bounds__(128, 3) void attn_kernel7(float* __restrict__ out)
{
    extern __shared__ __half smh[];
    __half* Qs = smh;
    const uint32_t sbase = smem_u32(smh);
    const uint32_t kbase = sbase + HOFF_K * 2;
    const uint32_t vbase = sbase + HOFF_V * 2;

    const int tid  = threadIdx.x;
    const int wid  = tid >> 5;
    const int lane = tid & 31;
    const int g    = lane >> 2;
    const int t    = lane & 3;
    const int warpQ = wid * 32;
    const int lr8 = lane & 7;             // ldmatrix row within 8-block
    const int h8  = (lane >> 3) & 1;      // matrix-pair selector
    const int h16 = (lane >> 4) & 1;

    const int bh = blockIdx.y;
    const int bi = bh >> 4;
    const int h  = bh & 15;
    const int q0 = blockIdx.x * 128;

    const __half* Qg = g_q + (size_t)bh * N_ * HD_ + (size_t)q0 * HD_;
    const __half* Kg = g_k + (size_t)bh * N_ * HD_;
    const __half* Vg = g_v + (size_t)bh * N_ * HD_;

    // load Q 128x64 halves (rows of 128B, 8x16B chunks)
    #pragma unroll
    for (int s = 0; s < 8; s++) {
        int slot = tid + s * 128;
        int row = slot >> 3;
        int c8  = (slot & 7) * 8;
        *(float4*)(Qs + row * QSTRH + c8) = *(const float4*)(Qg + row * HD_ + c8);
    }

    // ldmatrix base offsets (bytes), col part added per kst
    // Q a-frag: rows warpQ+16mt + lr8 + 8*h8 ; col block 8*h16
    // K b-frag (x4 = nt pair): row 16ntp + 8*h16 + lr8 ; col block 8*h8
    // V b-frag (x4t): row(key) 16kst + 8*h8 + lr8 ; col 16ntp + 8*h16

    float o[2][8][4];
    float mrow[2][2], lrow[2][2];
    #pragma unroll
    for (int mt = 0; mt < 2; mt++) {
        mrow[mt][0] = -1e30f; mrow[mt][1] = -1e30f;
        lrow[mt][0] = 0.0f;   lrow[mt][1] = 0.0f;
        #pragma unroll
        for (int nt = 0; nt < 8; nt++)
            #pragma unroll
            for (int r = 0; r < 4; r++) o[mt][nt][r] = 0.0f;
    }

    for (int kt = 0; kt < N_ / 64; kt++) {
        __syncthreads();
        // K/V tiles: 64 rows x 64 halves each; 8 cp16 chunks per thread
        #pragma unroll
        for (int s = 0; s < 4; s++) {
            int slot = tid + s * 128;
            int row = slot >> 3;
            int c8  = (slot & 7) * 8;
            cpasync16(kbase + (uint32_t)((row * KSTRH + c8) * 2),
                      Kg + (size_t)(kt * 64 + row) * HD_ + c8);
            cpasync16(vbase + (uint32_t)((row * VSTRH + c8) * 2),
                      Vg + (size_t)(kt * 64 + row) * HD_ + c8);
        }
        asm volatile("cp.async.commit_group;" ::: "memory");
        asm volatile("cp.async.wait_group 0;" ::: "memory");
        __syncthreads();

        // stage 1: S = Q K^T  (fp16 mma, warp: 32q x 64k)
        float s_[2][8][4];
        #pragma unroll
        for (int mt = 0; mt < 2; mt++)
            #pragma unroll
            for (int nt = 0; nt < 8; nt++)
                #pragma unroll
                for (int r = 0; r < 4; r++) s_[mt][nt][r] = 0.0f;

        #pragma unroll
        for (int kst = 0; kst < 4; kst++) {
            uint32_t aq[2][4];
            #pragma unroll
            for (int mt = 0; mt < 2; mt++)
                ldsm_x4(aq[mt], sbase + (uint32_t)(((warpQ + 16 * mt + lr8 + 8 * h8) * QSTRH
                                                    + kst * 16 + 8 * h16) * 2));
            #pragma unroll
            for (int ntp = 0; ntp < 4; ntp++) {
                uint32_t bk[4];
                ldsm_x4(bk, kbase + (uint32_t)(((16 * ntp + 8 * h16 + lr8) * KSTRH
                                               + kst * 16 + 8 * h8) * 2));
                #pragma unroll
                for (int mt = 0; mt < 2; mt++) {
                    mma16(s_[mt][2 * ntp],     aq[mt][0], aq[mt][1], aq[mt][2], aq[mt][3], bk[0], bk[1]);
                    mma16(s_[mt][2 * ntp + 1], aq[mt][0], aq[mt][1], aq[mt][2], aq[mt][3], bk[2], bk[3]);
                }
            }
        }

        // online softmax (P kept in s_ as f32; rounded at pack time)
        #pragma unroll
        for (int mt = 0; mt < 2; mt++) {
            float mx0 = -1e30f, mx1 = -1e30f;
            #pragma unroll
            for (int nt = 0; nt < 8; nt++) {
                mx0 = fmaxf(mx0, fmaxf(s_[mt][nt][0], s_[mt][nt][1]));
                mx1 = fmaxf(mx1, fmaxf(s_[mt][nt][2], s_[mt][nt][3]));
            }
            mx0 = fmaxf(mx0, __shfl_xor_sync(0xffffffffu, mx0, 1));
            mx0 = fmaxf(mx0, __shfl_xor_sync(0xffffffffu, mx0, 2));
            mx1 = fmaxf(mx1, __shfl_xor_sync(0xffffffffu, mx1, 1));
            mx1 = fmaxf(mx1, __shfl_xor_sync(0xffffffffu, mx1, 2));
            const float nm0 = fmaxf(mrow[mt][0], mx0);
            const float nm1 = fmaxf(mrow[mt][1], mx1);
            const float corr0 = __expf(mrow[mt][0] - nm0);
            const float corr1 = __expf(mrow[mt][1] - nm1);
            mrow[mt][0] = nm0; mrow[mt][1] = nm1;

            float rs0 = 0.0f, rs1 = 0.0f;
            #pragma unroll
            for (int nt = 0; nt < 8; nt++) {
                float p0 = __expf(s_[mt][nt][0] - nm0);
                float p1 = __expf(s_[mt][nt][1] - nm0);
                float p2 = __expf(s_[mt][nt][2] - nm1);
                float p3 = __expf(s_[mt][nt][3] - nm1);
                rs0 += p0 + p1;  rs1 += p2 + p3;
                s_[mt][nt][0] = p0; s_[mt][nt][1] = p1;
                s_[mt][nt][2] = p2; s_[mt][nt][3] = p3;
            }
            rs0 += __shfl_xor_sync(0xffffffffu, rs0, 1);
            rs0 += __shfl_xor_sync(0xffffffffu, rs0, 2);
            rs1 += __shfl_xor_sync(0xffffffffu, rs1, 1);
            rs1 += __shfl_xor_sync(0xffffffffu, rs1, 2);
            lrow[mt][0] = lrow[mt][0] * corr0 + rs0;
            lrow[mt][1] = lrow[mt][1] * corr1 + rs1;

            #pragma unroll
            for (int nt = 0; nt < 8; nt++) {
                o[mt][nt][0] *= corr0; o[mt][nt][1] *= corr0;
                o[mt][nt][2] *= corr1; o[mt][nt][3] *= corr1;
            }
        }

        // stage 2: O += P V ; P a-frags packed directly from S c-frags,
        // V b-frags via ldmatrix.trans
        #pragma unroll
        for (int kst = 0; kst < 4; kst++) {
            uint32_t ap[2][4];
            #pragma unroll
            for (int mt = 0; mt < 2; mt++) {
                ap[mt][0] = packh2(s_[mt][2 * kst][0],     s_[mt][2 * kst][1]);
                ap[mt][1] = packh2(s_[mt][2 * kst][2],     s_[mt][2 * kst][3]);
                ap[mt][2] = packh2(s_[mt][2 * kst + 1][0], s_[mt][2 * kst + 1][1]);
                ap[mt][3] = packh2(s_[mt][2 * kst + 1][2], s_[mt][2 * kst + 1][3]);
            }
            #pragma unroll
            for (int ntp = 0; ntp < 4; ntp++) {
                uint32_t bv[4];
                ldsm_x4t(bv, vbase + (uint32_t)(((16 * kst + 8 * h8 + lr8) * VSTRH
                                                + 16 * ntp + 8 * h16) * 2));
                #pragma unroll
                for (int mt = 0; mt < 2; mt++) {
                    mma16(o[mt][2 * ntp],     ap[mt][0], ap[mt][1], ap[mt][2], ap[mt][3], bv[0], bv[1]);
                    mma16(o[mt][2 * ntp + 1], ap[mt][0], ap[mt][1], ap[mt][2], ap[mt][3], bv[2], bv[3]);
                }
            }
        }
    }

    // normalize + store
    #pragma unroll
    for (int mt = 0; mt < 2; mt++) {
        const float inv0 = 1.0f / lrow[mt][0];
        const float inv1 = 1.0f / lrow[mt][1];
        const int n0 = q0 + warpQ + mt * 16 + g;
        float* po0 = out + ((size_t)bi * N_ + n0) * DIM_ + h * HD_;
        float* po1 = out + ((size_t)bi * N_ + n0 + 8) * DIM_ + h * HD_;
        #pragma unroll
        for (int nt = 0; nt < 8; nt++) {
            const int c = nt * 8 + 2 * t;
            *(float2*)(po0 + c) = make_float2(o[mt][nt][0] * inv0, o[mt][nt][1] * inv0);
            *(float2*)(po1 + c) = make_float2(o[mt][nt][2] * inv1, o[mt][nt][3] * inv1);
        }
    }
}

// ---------------------------------------------------------------------------
extern "C" void kernel_launch(void* const* d_in, const int* in_sizes, int n_in,
                              void* d_out, int out_size)
{
    const float* x    = (const float*)d_in[0];
    const float* wqkv = (const float*)d_in[1];
    const float* bqkv = (const float*)d_in[2];
    float* out = (float*)d_out;

    cudaFuncSetAttribute(qkv_mma_kernel,
                         cudaFuncAttributeMaxDynamicSharedMemorySize, G_SMEM_BYTES);
    cudaFuncSetAttribute(attn_kernel7,
                         cudaFuncAttributeMaxDynamicSharedMemorySize, ATT_SMEM);

    dim3 ggrid(E3_ / 128, M_ / 256);   // (24, 32)
    qkv_mma_kernel<<<ggrid, 512, G_SMEM_BYTES>>>(x, wqkv, bqkv);

    dim3 agrid(N_ / 128, B_ * H_);     // (16, 64)
    attn_kernel7<<<agrid, 128, ATT_SMEM>>>(out);
}

// round 11
// speedup vs baseline: 2.5660x; 1.7853x over previous
#include <cuda_runtime.h>
#include <cuda_fp16.h>
#include <cstdint>

#define B_   4
#define N_   2048
#define DIM_ 1024
#define H_   16
#define HD_  64
#define E3_  3072
#define M_   8192
#define SCALE_ 0.125f

// fp16 scratch
__device__ __half g_xh[(size_t)M_ * DIM_];
__device__ __half g_wh[(size_t)E3_ * DIM_];
__device__ __half g_q[(size_t)B_ * H_ * N_ * HD_];
__device__ __half g_k[(size_t)B_ * H_ * N_ * HD_];
__device__ __half g_v[(size_t)B_ * H_ * N_ * HD_];

// ---------------------------------------------------------------------------
// helpers
// ---------------------------------------------------------------------------
__device__ __forceinline__ uint32_t smem_u32(const void* p) {
    uint32_t a;
    asm("{ .reg .u64 t; cvta.to.shared.u64 t, %1; cvt.u32.u64 %0, t; }"
        : "=r"(a) : "l"(p));
    return a;
}
__device__ __forceinline__ void cpasync16(uint32_t dst, const void* src) {
    asm volatile("cp.async.cg.shared.global [%0], [%1], 16;"
                 :: "r"(dst), "l"(src) : "memory");
}
// fp16: d += a(16x16) * b(16x8), f32 accum
__device__ __forceinline__ void mma16(float* d,
                                      uint32_t a0, uint32_t a1, uint32_t a2, uint32_t a3,
                                      uint32_t b0, uint32_t b1) {
    asm volatile(
        "mma.sync.aligned.m16n8k16.row.col.f32.f16.f16.f32 "
        "{%0,%1,%2,%3}, {%4,%5,%6,%7}, {%8,%9}, {%0,%1,%2,%3};"
        : "+f"(d[0]), "+f"(d[1]), "+f"(d[2]), "+f"(d[3])
        : "r"(a0), "r"(a1), "r"(a2), "r"(a3), "r"(b0), "r"(b1));
}
__device__ __forceinline__ void ldsm_x4(uint32_t* r, uint32_t addr) {
    asm volatile("ldmatrix.sync.aligned.m8n8.x4.shared.b16 {%0,%1,%2,%3}, [%4];"
                 : "=r"(r[0]), "=r"(r[1]), "=r"(r[2]), "=r"(r[3]) : "r"(addr));
}
__device__ __forceinline__ void ldsm_x4t(uint32_t* r, uint32_t addr) {
    asm volatile("ldmatrix.sync.aligned.m8n8.x4.trans.shared.b16 {%0,%1,%2,%3}, [%4];"
                 : "=r"(r[0]), "=r"(r[1]), "=r"(r[2]), "=r"(r[3]) : "r"(addr));
}
__device__ __forceinline__ uint32_t packh2(float lo, float hi) {
    __half2 h = __floats2half2_rn(lo, hi);
    return *(uint32_t*)&h;
}

// ---------------------------------------------------------------------------
// Kernel 0: fp32 -> fp16 conversion (X and W scratch)
// ---------------------------------------------------------------------------
__global__ void cvt_fp16_kernel(const float4* __restrict__ in,
                                __half* __restrict__ out, int n4) {
    int i = blockIdx.x * blockDim.x + threadIdx.x;
    if (i >= n4) return;
    float4 v = in[i];
    __half2 a = __floats2half2_rn(v.x, v.y);
    __half2 b = __floats2half2_rn(v.z, v.w);
    *(uint2*)(out + 4 * (size_t)i) = make_uint2(*(uint32_t*)&a, *(uint32_t*)&b);
}

// ---------------------------------------------------------------------------
// Kernel 1: QKV projection, fp16 mma m16n8k16 + ldmatrix.
// C[m][e] = sum_d Xh[m][d]*Wh[e][d] + bias[e] -> scatter fp16 g_q/g_k/g_v.
// CTA 128x128, BK=64 double-buffered cp.async, 256 thr, 8 warps (4m x 2n),
// warp tile 32(m) x 64(n). smem stride 72 halves. 73728 B.
// ---------------------------------------------------------------------------
#define QK_STR 72
#define QT_TILE (128 * QK_STR)        // halves per buffer
#define QOFF_A1 QT_TILE
#define QOFF_B0 (2 * QT_TILE)
#define QOFF_B1 (3 * QT_TILE)
#define QG_SMEM (4 * QT_TILE * 2)     // 73728 B

__global__ __launch_bounds__(256) void qkv_h_kernel(
    const __half* __restrict__ Xh, const __half* __restrict__ Wh,
    const float* __restrict__ bias)
{
    extern __shared__ __half smq[];
    const uint32_t sbase = smem_u32(smq);

    const int tid  = threadIdx.x;
    const int wid  = tid >> 5;
    const int lane = tid & 31;
    const int g    = lane >> 2;
    const int t    = lane & 3;
    const int lr8  = lane & 7;
    const int h8   = (lane >> 3) & 1;
    const int h16  = (lane >> 4) & 1;
    const int warpM = (wid >> 1) * 32;   // 0,32,64,96
    const int warpN = (wid & 1) * 64;    // 0,64
    const int mBase = blockIdx.y * 128;
    const int eBase = blockIdx.x * 128;

    // loader: 1024 16B-chunks per (A or B) stage, 256 thr -> 4 each
    auto load_stage = [&](int buf, int s) {
        const int k0 = s * 64;
        #pragma unroll
        for (int c = 0; c < 4; c++) {
            int slot = tid + c * 256;
            int row = slot >> 3;
            int c8  = (slot & 7) * 8;
            cpasync16(sbase + (uint32_t)(((buf ? QOFF_A1 : 0) + row * QK_STR + c8) * 2),
                      Xh + (size_t)(mBase + row) * DIM_ + k0 + c8);
            cpasync16(sbase + (uint32_t)(((buf ? QOFF_B1 : QOFF_B0) + row * QK_STR + c8) * 2),
                      Wh + (size_t)(eBase + row) * DIM_ + k0 + c8);
        }
        asm volatile("cp.async.commit_group;" ::: "memory");
    };

    float acc[2][8][4];
    #pragma unroll
    for (int i = 0; i < 2; i++)
        #pragma unroll
        for (int j = 0; j < 8; j++)
            #pragma unroll
            for (int r = 0; r < 4; r++) acc[i][j][r] = 0.0f;

    load_stage(0, 0);
    load_stage(1, 1);

    const int NS = DIM_ / 64;   // 16
    for (int s = 0; s < NS; s++) {
        const int buf = s & 1;
        if (s < NS - 1) asm volatile("cp.async.wait_group 1;" ::: "memory");
        else            asm volatile("cp.async.wait_group 0;" ::: "memory");
        __syncthreads();

        const uint32_t abase = sbase + (uint32_t)((buf ? QOFF_A1 : 0) * 2);
        const uint32_t bbase = sbase + (uint32_t)((buf ? QOFF_B1 : QOFF_B0) * 2);

        #pragma unroll
        for (int kst = 0; kst < 4; kst++) {
            uint32_t aq[2][4];
            #pragma unroll
            for (int mt = 0; mt < 2; mt++)
                ldsm_x4(aq[mt], abase + (uint32_t)(((warpM + 16 * mt + lr8 + 8 * h8) * QK_STR
                                                    + kst * 16 + 8 * h16) * 2));
            #pragma unroll
            for (int ntp = 0; ntp < 4; ntp++) {
                uint32_t bk[4];
                ldsm_x4(bk, bbase + (uint32_t)(((warpN + 16 * ntp + 8 * h16 + lr8) * QK_STR
                                               + kst * 16 + 8 * h8) * 2));
                #pragma unroll
                for (int mt = 0; mt < 2; mt++) {
                    mma16(acc[mt][2 * ntp],     aq[mt][0], aq[mt][1], aq[mt][2], aq[mt][3], bk[0], bk[1]);
                    mma16(acc[mt][2 * ntp + 1], aq[mt][0], aq[mt][1], aq[mt][2], aq[mt][3], bk[2], bk[3]);
                }
            }
        }
        __syncthreads();
        if (s + 2 < NS) load_stage(buf, s + 2);
    }

    // epilogue: bias + scale + fp16 round + scatter
    #pragma unroll
    for (int nt = 0; nt < 8; nt++) {
        const int c0   = eBase + warpN + nt * 8 + 2 * t;
        const int tsel = c0 >> 10;
        const int rem  = c0 & (DIM_ - 1);
        const int h    = rem >> 6;
        const int hd   = rem & (HD_ - 1);
        __half* dst = (tsel == 0) ? g_q : ((tsel == 1) ? g_k : g_v);
        const float sc = (tsel == 0) ? SCALE_ : 1.0f;
        const float bb0 = __ldg(bias + c0);
        const float bb1 = __ldg(bias + c0 + 1);
        #pragma unroll
        for (int mt = 0; mt < 2; mt++) {
            const int r0 = mBase + warpM + mt * 16 + g;
            #pragma unroll
            for (int half = 0; half < 2; half++) {
                const int row = r0 + half * 8;
                const int bi  = row >> 11;
                const int n   = row & (N_ - 1);
                __half2 hv = __floats2half2_rn(
                    (acc[mt][nt][half * 2 + 0] + bb0) * sc,
                    (acc[mt][nt][half * 2 + 1] + bb1) * sc);
                *(__half2*)(dst + ((((size_t)bi * H_ + h) * N_ + n) * HD_ + hd)) = hv;
            }
        }
    }
}

// ---------------------------------------------------------------------------
// Kernel 2: flash attention (unchanged from R10 pass).
// ---------------------------------------------------------------------------
#define QSTRH 72
#define KSTRH 72
#define VSTRH 72
#define HOFF_K (128 * QSTRH)
#define HOFF_V (HOFF_K + 64 * KSTRH)
#define ATT_SMEM ((HOFF_V + 64 * VSTRH) * 2)   // 36864 B

__global__ __launch_bounds__(128, 3) void attn_kernel7(float* __restrict__ out)
{
    extern __shared__ __half smh[];
    __half* Qs = smh;
    const uint32_t sbase = smem_u32(smh);
    const uint32_t kbase = sbase + HOFF_K * 2;
    const uint32_t vbase = sbase + HOFF_V * 2;

    const int tid  = threadIdx.x;
    const int wid  = tid >> 5;
    const int lane = tid & 31;
    const int g    = lane >> 2;
    const int t    = lane & 3;
    const int warpQ = wid * 32;
    const int lr8 = lane & 7;
    const int h8  = (lane >> 3) & 1;
    const int h16 = (lane >> 4) & 1;

    const int bh = blockIdx.y;
    const int bi = bh >> 4;
    const int h  = bh & 15;
    const int q0 = blockIdx.x * 128;

    const __half* Qg = g_q + (size_t)bh * N_ * HD_ + (size_t)q0 * HD_;
    const __half* Kg = g_k + (size_t)bh * N_ * HD_;
    const __half* Vg = g_v + (size_t)bh * N_ * HD_;

    #pragma unroll
    for (int s = 0; s < 8; s++) {
        int slot = tid + s * 128;
        int row = slot >> 3;
        int c8  = (slot & 7) * 8;
        *(float4*)(Qs + row * QSTRH + c8) = *(const float4*)(Qg + row * HD_ + c8);
    }

    float o[2][8][4];
    float mrow[2][2], lrow[2][2];
    #pragma unroll
    for (int mt = 0; mt < 2; mt++) {
        mrow[mt][0] = -1e30f; mrow[mt][1] = -1e30f;
        lrow[mt][0] = 0.0f;   lrow[mt][1] = 0.0f;
        #pragma unroll
        for (int nt = 0; nt < 8; nt++)
            #pragma unroll
            for (int r = 0; r < 4; r++) o[mt][nt][r] = 0.0f;
    }

    for (int kt = 0; kt < N_ / 64; kt++) {
        __syncthreads();
        #pragma unroll
        for (int s = 0; s < 4; s++) {
            int slot = tid + s * 128;
            int row = slot >> 3;
            int c8  = (slot & 7) * 8;
            cpasync16(kbase + (uint32_t)((row * KSTRH + c8) * 2),
                      Kg + (size_t)(kt * 64 + row) * HD_ + c8);
            cpasync16(vbase + (uint32_t)((row * VSTRH + c8) * 2),
                      Vg + (size_t)(kt * 64 + row) * HD_ + c8);
        }
        asm volatile("cp.async.commit_group;" ::: "memory");
        asm volatile("cp.async.wait_group 0;" ::: "memory");
        __syncthreads();

        float s_[2][8][4];
        #pragma unroll
        for (int mt = 0; mt < 2; mt++)
            #pragma unroll
            for (int nt = 0; nt < 8; nt++)
                #pragma unroll
                for (int r = 0; r < 4; r++) s_[mt][nt][r] = 0.0f;

        #pragma unroll
        for (int kst = 0; kst < 4; kst++) {
            uint32_t aq[2][4];
            #pragma unroll
            for (int mt = 0; mt < 2; mt++)
                ldsm_x4(aq[mt], sbase + (uint32_t)(((warpQ + 16 * mt + lr8 + 8 * h8) * QSTRH
                                                    + kst * 16 + 8 * h16) * 2));
            #pragma unroll
            for (int ntp = 0; ntp < 4; ntp++) {
                uint32_t bk[4];
                ldsm_x4(bk, kbase + (uint32_t)(((16 * ntp + 8 * h16 + lr8) * KSTRH
                                               + kst * 16 + 8 * h8) * 2));
                #pragma unroll
                for (int mt = 0; mt < 2; mt++) {
                    mma16(s_[mt][2 * ntp],     aq[mt][0], aq[mt][1], aq[mt][2], aq[mt][3], bk[0], bk[1]);
                    mma16(s_[mt][2 * ntp + 1], aq[mt][0], aq[mt][1], aq[mt][2], aq[mt][3], bk[2], bk[3]);
                }
            }
        }

        #pragma unroll
        for (int mt = 0; mt < 2; mt++) {
            float mx0 = -1e30f, mx1 = -1e30f;
            #pragma unroll
            for (int nt = 0; nt < 8; nt++) {
                mx0 = fmaxf(mx0, fmaxf(s_[mt][nt][0], s_[mt][nt][1]));
                mx1 = fmaxf(mx1, fmaxf(s_[mt][nt][2], s_[mt][nt][3]));
            }
            mx0 = fmaxf(mx0, __shfl_xor_sync(0xffffffffu, mx0, 1));
            mx0 = fmaxf(mx0, __shfl_xor_sync(0xffffffffu, mx0, 2));
            mx1 = fmaxf(mx1, __shfl_xor_sync(0xffffffffu, mx1, 1));
            mx1 = fmaxf(mx1, __shfl_xor_sync(0xffffffffu, mx1, 2));
            const float nm0 = fmaxf(mrow[mt][0], mx0);
            const float nm1 = fmaxf(mrow[mt][1], mx1);
            const float corr0 = __expf(mrow[mt][0] - nm0);
            const float corr1 = __expf(mrow[mt][1] - nm1);
            mrow[mt][0] = nm0; mrow[mt][1] = nm1;

            float rs0 = 0.0f, rs1 = 0.0f;
            #pragma unroll
            for (int nt = 0; nt < 8; nt++) {
                float p0 = __expf(s_[mt][nt][0] - nm0);
                float p1 = __expf(s_[mt][nt][1] - nm0);
                float p2 = __expf(s_[mt][nt][2] - nm1);
                float p3 = __expf(s_[mt][nt][3] - nm1);
                rs0 += p0 + p1;  rs1 += p2 + p3;
                s_[mt][nt][0] = p0; s_[mt][nt][1] = p1;
                s_[mt][nt][2] = p2; s_[mt][nt][3] = p3;
            }
            rs0 += __shfl_xor_sync(0xffffffffu, rs0, 1);
            rs0 += __shfl_xor_sync(0xffffffffu, rs0, 2);
            rs1 += __shfl_xor_sync(0xffffffffu, rs1, 1);
            rs1 += __shfl_xor_sync(0xffffffffu, rs1, 2);
            lrow[mt][0] = lrow[mt][0] * corr0 + rs0;
            lrow[mt][1] = lrow[mt][1] * corr1 + rs1;

            #pragma unroll
            for (int nt = 0; nt < 8; nt++) {
                o[mt][nt][0] *= corr0; o[mt][nt][1] *= corr0;
                o[mt][nt][2] *= corr1; o[mt][nt][3] *= corr1;
            }
        }

        #pragma unroll
        for (int kst = 0; kst < 4; kst++) {
            uint32_t ap[2][4];
            #pragma unroll
            for (int mt = 0; mt < 2; mt++) {
                ap[mt][0] = packh2(s_[mt][2 * kst][0],     s_[mt][2 * kst][1]);
                ap[mt][1] = packh2(s_[mt][2 * kst][2],     s_[mt][2 * kst][3]);
                ap[mt][2] = packh2(s_[mt][2 * kst + 1][0], s_[mt][2 * kst + 1][1]);
                ap[mt][3] = packh2(s_[mt][2 * kst + 1][2], s_[mt][2 * kst + 1][3]);
            }
            #pragma unroll
            for (int ntp = 0; ntp < 4; ntp++) {
                uint32_t bv[4];
                ldsm_x4t(bv, vbase + (uint32_t)(((16 * kst + 8 * h8 + lr8) * VSTRH
                                                + 16 * ntp + 8 * h16) * 2));
                #pragma unroll
                for (int mt = 0; mt < 2; mt++) {
                    mma16(o[mt][2 * ntp],     ap[mt][0], ap[mt][1], ap[mt][2], ap[mt][3], bv[0], bv[1]);
                    mma16(o[mt][2 * ntp + 1], ap[mt][0], ap[mt][1], ap[mt][2], ap[mt][3], bv[2], bv[3]);
                }
            }
        }
    }

    #pragma unroll
    for (int mt = 0; mt < 2; mt++) {
        const float inv0 = 1.0f / lrow[mt][0];
        const float inv1 = 1.0f / lrow[mt][1];
        const int n0 = q0 + warpQ + mt * 16 + g;
        float* po0 = out + ((size_t)bi * N_ + n0) * DIM_ + h * HD_;
        float* po1 = out + ((size_t)bi * N_ + n0 + 8) * DIM_ + h * HD_;
        #pragma unroll
        for (int nt = 0; nt < 8; nt++) {
            const int c = nt * 8 + 2 * t;
            *(float2*)(po0 + c) = make_float2(o[mt][nt][0] * inv0, o[mt][nt][1] * inv0);
            *(float2*)(po1 + c) = make_float2(o[mt][nt][2] * inv1, o[mt][nt][3] * inv1);
        }
    }
}

// ---------------------------------------------------------------------------
extern "C" void kernel_launch(void* const* d_in, const int* in_sizes, int n_in,
                              void* d_out, int out_size)
{
    const float* x    = (const float*)d_in[0];
    const float* wqkv = (const float*)d_in[1];
    const float* bqkv = (const float*)d_in[2];
    float* out = (float*)d_out;

    __half *xh, *wh;
    cudaGetSymbolAddress((void**)&xh, g_xh);
    cudaGetSymbolAddress((void**)&wh, g_wh);

    cudaFuncSetAttribute(qkv_h_kernel,
                         cudaFuncAttributeMaxDynamicSharedMemorySize, QG_SMEM);
    cudaFuncSetAttribute(attn_kernel7,
                         cudaFuncAttributeMaxDynamicSharedMemorySize, ATT_SMEM);

    // 0) fp32 -> fp16
    int n4x = (M_ * DIM_) / 4;
    int n4w = (E3_ * DIM_) / 4;
    cvt_fp16_kernel<<<(n4x + 255) / 256, 256>>>((const float4*)x, xh, n4x);
    cvt_fp16_kernel<<<(n4w + 255) / 256, 256>>>((const float4*)wqkv, wh, n4w);

    // 1) QKV projection (fp16 tensor cores)
    dim3 ggrid(E3_ / 128, M_ / 128);   // (24, 64)
    qkv_h_kernel<<<ggrid, 256, QG_SMEM>>>(xh, wh, bqkv);

    // 2) flash attention
    dim3 agrid(N_ / 128, B_ * H_);     // (16, 64)
    attn_kernel7<<<agrid, 128, ATT_SMEM>>>(out);
}